// round 11
// baseline (speedup 1.0000x reference)
#include <cuda_runtime.h>
#include <math.h>
#include <stdint.h>

// BuildingModule: 3-state RC thermal scan, B=8192 chains x 1023 serial steps.
// 64-thread blocks = 2 independent compute+IO warps (32 chains each) on
// SMSP0/SMSP1 (issue-bound regime: 256 warps = 256 issue ports, saturated).
// This revision minimizes issue slots per step:
//   - drain addressing (12 coalesced 16B units of chunk c-1) fully hoisted:
//     precomputed smem offsets + gmem pointers, advanced 192B per chunk
//   - u: 3-deep smem ring, 2 cp.async per step (stage chunk c+2)
//   - out: 4-step register buffer -> 3x STS.128 (conflict-free stride 52)
// Math: incremental reciprocal (cubic poly for 2^-m), kl-prefolded coeffs.

#define BATCH   8192
#define TSTEPS  1024
#define CHUNK   16
#define NCHUNK  (TSTEPS / CHUNK)        // 64
#define ROWW    132                     // words: 128 data + 4 pad
#define OROWW   52                      // words: 48 data + 4 pad
#define USTRIDE (TSTEPS * 8)            // floats per chain in u
#define OSTRIDE (TSTEPS * 3)            // floats per chain in out

#define UBUF_WORDS (32 * ROWW)          // one u ring slot   (16896 B)
#define OBUF_WORDS (32 * OROWW)         // one out buffer    ( 6656 B)
#define OBUF_BYTES (OBUF_WORDS * 4)
#define WARP_WORDS (3 * UBUF_WORDS + 2 * OBUF_WORDS)
#define SMEM_BYTES (2 * WARP_WORDS * 4) // 127744 B per block

__device__ __forceinline__ void cpa16(uint32_t s, const float* g) {
    asm volatile("cp.async.cg.shared.global [%0], [%1], 16;" :: "r"(s), "l"(g));
}
__device__ __forceinline__ void cpa_commit() {
    asm volatile("cp.async.commit_group;" ::: "memory");
}
__device__ __forceinline__ void cpa_wait1() {
    asm volatile("cp.async.wait_group 1;" ::: "memory");
}
__device__ __forceinline__ float rcpa(float x) {
    float y; asm("rcp.approx.ftz.f32 %0, %1;" : "=f"(y) : "f"(x)); return y;
}
__device__ __forceinline__ float ex2a(float x) {
    float y; asm("ex2.approx.ftz.f32 %0, %1;" : "=f"(y) : "f"(x)); return y;
}
__device__ __forceinline__ float4 lds128(uint32_t a) {
    float4 v;
    asm volatile("ld.shared.v4.f32 {%0,%1,%2,%3}, [%4];"
                 : "=f"(v.x), "=f"(v.y), "=f"(v.z), "=f"(v.w) : "r"(a));
    return v;
}

extern __shared__ float smem[];

__global__ void __launch_bounds__(64)
bm_kernel(const float* __restrict__ x0g,
          const float* __restrict__ ug,
          const float* __restrict__ lamg,
          float* __restrict__ outg)
{
    const int tid  = threadIdx.x;
    const int lane = tid & 31;
    const int wid  = tid >> 5;                 // 0 or 1 -> SMSP 0 / 1
    const int b0   = blockIdx.x * 64 + wid * 32;
    const int b    = b0 + lane;

    float* ub = smem + wid * WARP_WORDS;       // [3][32*ROWW] ring
    float* ob = ub + 3 * UBUF_WORDS;           // [2][32*OROWW]
    const uint32_t ubS = (uint32_t)__cvta_generic_to_shared(ub);
    const uint32_t obS = (uint32_t)__cvta_generic_to_shared(ob);

    const float e12 = expf(lamg[0]);
    const float e23 = expf(lamg[1]);
    const float ee0 = expf(lamg[2]),  ee1 = expf(lamg[3]),  ee2 = expf(lamg[4]);
    const float es0 = expf(lamg[5]),  es1 = expf(lamg[6]),  es2 = expf(lamg[7]);
    const float eh0 = expf(lamg[8]),  eh1 = expf(lamg[9]),  eh2 = expf(lamg[10]);
    const float ec0 = expf(lamg[11]), ec1 = expf(lamg[12]), ec2 = expf(lamg[13]);

    const float kl0 = (float)(60.0 / 10665991.0 * 1.4426950408889634);
    const float kl1 = (float)(60.0 / 27000000.0 * 1.4426950408889634);
    const float kl2 = (float)(60.0 /  7953253.0 * 1.4426950408889634);

    const float g12_0  =  kl0 * e12;
    const float ng12_1 = -kl1 * e12;
    const float g23_1  =  kl1 * e23;
    const float ng23_2 = -kl2 * e23;
    const float eeK0 = kl0*ee0, eeK1 = kl1*ee1, eeK2 = kl2*ee2;
    const float neeK0 = -eeK0, neeK1 = -eeK1, neeK2 = -eeK2;
    const float esK0 = kl0*es0, esK1 = kl1*es1, esK2 = kl2*es2;
    const float ehK0 = kl0*eh0, ehK1 = kl1*eh1, ehK2 = kl2*eh2;
    const float ecK0 = kl0*ec0, ecK1 = kl1*ec1, ecK2 = kl2*ec2;

    float x0 = x0g[b * 3 + 0];
    float x1 = x0g[b * 3 + 1];
    float x2 = x0g[b * 3 + 2];
    float i0 = rcpa(x0), i1 = rcpa(x1), i2 = rcpa(x2);
    i0 = i0 * (2.0f - x0 * i0);
    i1 = i1 * (2.0f - x1 * i1);
    i2 = i2 * (2.0f - x2 * i2);

    const float* up0 = ug + (size_t)b0 * USTRIDE;   // warp's chain-0 u base

    // ---- precomputed drain mapping (chunk-invariant; ptrs advance 48 fl) ----
    uint32_t dsm[12];      // smem byte offset within ob[0]
    float*   dgp[12];      // gmem pointer for chunk 0's drain slot
#pragma unroll
    for (int it = 0; it < 12; it++) {
        const int unit  = it * 32 + lane;
        const int chain = unit / 12;
        const int o     = unit - chain * 12;
        dsm[it] = (uint32_t)((chain * OROWW + o * 4) * 4);
        dgp[it] = outg + (size_t)(b0 + chain) * OSTRIDE + o * 4;
    }

    // Serialized staging for priming only.
#define STAGE_FULL(C, SLOT) do {                                              \
    uint32_t s = ubS + (SLOT) * (UBUF_WORDS * 4) + lane * 16;                 \
    const float* g = up0 + (size_t)(C) * (CHUNK * 8) + lane * 4;              \
    _Pragma("unroll")                                                         \
    for (int i_ = 0; i_ < 32; i_++) {                                         \
        cpa16(s, g);                                                          \
        s += ROWW * 4;                                                        \
        g += USTRIDE;                                                         \
    }                                                                         \
    cpa_commit();                                                             \
} while (0)

    STAGE_FULL(0, 0);
    STAGE_FULL(1, 1);
    cpa_wait1();               // chunk 0 resident
    __syncwarp();

    int rd = 0;                // ring slot holding chunk c
    for (int c = 0; c < NCHUNK; c++) {
        const int bo  = c & 1;               // ob buffer for this chunk
        const int wrs = (rd + 2 >= 3) ? rd - 1 : rd + 2;  // slot for chunk c+2
        const bool stage_on = (c + 2 < NCHUNK);
        const bool drain_on = (c > 0);

        const float*   row  = &ub[rd * UBUF_WORDS + lane * ROWW];
        float*         orow = &ob[bo * OBUF_WORDS + lane * OROWW];
        const uint32_t obpS = obS + (bo ^ 1) * OBUF_BYTES;   // smem src of drain
        const uint32_t ubN  = ubS + wrs * (UBUF_WORDS * 4) + lane * 16;
        const float*   usN  = up0 + (size_t)(c + 2) * (CHUNK * 8) + lane * 4;

        float sb[12];          // 4 steps x 3 comps, masked, reg-resident

        float4 ua = *(const float4*)(row);        // u0,u1,h0,h1
        float4 uc = *(const float4*)(row + 4);    // h2,c0,c1,c2

#pragma unroll
        for (int j = 0; j < CHUNK; j++) {
            // stage 2 chain-rows of chunk c+2 (engine-paced, off-chain)
            if (stage_on) {
                cpa16(ubN + (2*j)     * (ROWW * 4), usN + (size_t)(2*j)     * USTRIDE);
                cpa16(ubN + (2*j + 1) * (ROWW * 4), usN + (size_t)(2*j + 1) * USTRIDE);
            }
            // drain one coalesced 16B unit of chunk c-1 (precomputed addrs)
            if (drain_on && j < 12) {
                const float4 v = lds128(obpS + dsm[j]);
                *(float4*)(dgp[j]) = v;
            }

            float4 na, nc;
            if (j < CHUNK - 1) {
                na = *(const float4*)(row + (j + 1) * 8);
                nc = *(const float4*)(row + (j + 1) * 8 + 4);
            }

            // out row 16c+j <- current state, masked by u0 of this row
            {
                const bool nm = (c == 0) && (j == 0);
                const bool mv = !nm && (ua.x < 1e-6f);
                const int  s  = (j & 3) * 3;
                sb[s + 0] = mv ? -1.0f : x0;
                sb[s + 1] = mv ? -1.0f : x1;
                sb[s + 2] = mv ? -1.0f : x2;
            }

            // scan step consuming this u row
            const float u0 = ua.x, u1 = ua.y;
            // off-chain: u-only products (eu depends only on u0)
            const float eu0 = eeK0 * u0, eu1 = eeK1 * u0, eu2 = eeK2 * u0;
            const float d12 = i0 - i1;
            const float d23 = i1 - i2;
            const float w0 = fmaf(esK0, u1, fmaf(ehK0, ua.z, fmaf(ecK0, uc.y, neeK0)));
            const float w1 = fmaf(esK1, u1, fmaf(ehK1, ua.w, fmaf(ecK1, uc.z, neeK1)));
            const float w2 = fmaf(esK2, u1, fmaf(ehK2, uc.x, fmaf(ecK2, uc.w, neeK2)));
            const float q0 = fmaf(eu0, i0, w0);
            const float q1 = fmaf(eu1, i1, w1);
            const float q2 = fmaf(eu2, i2, w2);
            const float m0 = fmaf(g12_0  * d12, x1, q0);
            const float m1 = fmaf(g23_1  * d23, x2, fmaf(ng12_1 * d12, x0, q1));
            const float m2 = fmaf(ng23_2 * d23, x1, q2);
            const float r0 = fmaf(fmaf(fmaf(-0.05550410866f, m0, 0.24022650696f), m0, -0.69314718056f), m0, 1.0f);
            const float r1 = fmaf(fmaf(fmaf(-0.05550410866f, m1, 0.24022650696f), m1, -0.69314718056f), m1, 1.0f);
            const float r2 = fmaf(fmaf(fmaf(-0.05550410866f, m2, 0.24022650696f), m2, -0.69314718056f), m2, 1.0f);
            x0 *= ex2a(m0);  x1 *= ex2a(m1);  x2 *= ex2a(m2);
            i0 *= r0;        i1 *= r1;        i2 *= r2;

            ua = na; uc = nc;

            // flush 4 buffered steps: 3x STS.128, conflict-free at stride 52
            if ((j & 3) == 3) {
                float* dst = orow + (j - 3) * 3;
                *(float4*)(dst + 0) = make_float4(sb[0], sb[1], sb[2],  sb[3]);
                *(float4*)(dst + 4) = make_float4(sb[4], sb[5], sb[6],  sb[7]);
                *(float4*)(dst + 8) = make_float4(sb[8], sb[9], sb[10], sb[11]);
            }
        }

        // advance drain gmem pointers to the chunk just produced
        if (drain_on) {
#pragma unroll
            for (int it = 0; it < 12; it++) dgp[it] += CHUNK * 3;
        }

        cpa_commit();          // close group for chunk c+2 (possibly empty)
        cpa_wait1();           // chunk c+1 resident (c+2 may still fly)
        __syncwarp();          // ob[bo] visible for next chunk's cross-lane drain

        rd = (rd + 1 >= 3) ? 0 : rd + 1;
    }

    // drain the final chunk (NCHUNK-1, ob buffer 1) synchronously
    {
        const uint32_t oblS = obS + 1 * OBUF_BYTES;
#pragma unroll
        for (int it = 0; it < 12; it++) {
            const float4 v = lds128(oblS + dsm[it]);
            *(float4*)(dgp[it]) = v;
        }
    }
}

extern "C" void kernel_launch(void* const* d_in, const int* in_sizes, int n_in,
                              void* d_out, int out_size)
{
    const float* x0  = nullptr;
    const float* u   = nullptr;
    const float* lam = nullptr;
    for (int i = 0; i < n_in; i++) {
        if (in_sizes[i] == 14)               lam = (const float*)d_in[i];
        else if (in_sizes[i] == BATCH * 3)   x0  = (const float*)d_in[i];
        else                                 u   = (const float*)d_in[i];
    }
    cudaFuncSetAttribute(bm_kernel,
                         cudaFuncAttributeMaxDynamicSharedMemorySize,
                         SMEM_BYTES);
    bm_kernel<<<BATCH / 64, 64, SMEM_BYTES>>>(x0, u, lam, (float*)d_out);
}

// round 15
// speedup vs baseline: 1.1303x; 1.1303x over previous
#include <cuda_runtime.h>
#include <math.h>
#include <stdint.h>

// BuildingModule: 3-state RC thermal scan, B=8192 chains x 1023 serial steps.
// 64-thread blocks = 2 independent compute+IO warps (32 chains each) on
// SMSP0/SMSP1. Per-warp instruction stream minimized with packed f32x2 math:
// states (0,2) share one FFMA2 lane pair, state 1 stays scalar.
//   - u: 3-deep smem ring, 2 cp.async per step (stage chunk c+2)
//   - out: 4-step register buffer -> 3x STS.128 (conflict-free stride 52);
//          drain of chunk c-1 (12x LDS.128+STG.128) spread across steps
// Math: incremental reciprocal (cubic poly for 2^-m), kl-prefolded coeffs.

#define BATCH   8192
#define TSTEPS  1024
#define CHUNK   16
#define NCHUNK  (TSTEPS / CHUNK)        // 64
#define ROWW    132                     // words: 128 data + 4 pad
#define OROWW   52                      // words: 48 data + 4 pad
#define USTRIDE (TSTEPS * 8)            // floats per chain in u
#define OSTRIDE (TSTEPS * 3)            // floats per chain in out

#define UBUF_WORDS (32 * ROWW)          // one u ring slot   (16896 B)
#define OBUF_WORDS (32 * OROWW)         // one out buffer    ( 6656 B)
#define WARP_WORDS (3 * UBUF_WORDS + 2 * OBUF_WORDS)
#define SMEM_BYTES (2 * WARP_WORDS * 4) // 127744 B per block

typedef unsigned long long u64;

__device__ __forceinline__ void cpa16(uint32_t s, const float* g) {
    asm volatile("cp.async.cg.shared.global [%0], [%1], 16;" :: "r"(s), "l"(g));
}
__device__ __forceinline__ void cpa_commit() {
    asm volatile("cp.async.commit_group;" ::: "memory");
}
__device__ __forceinline__ void cpa_wait1() {
    asm volatile("cp.async.wait_group 1;" ::: "memory");
}
__device__ __forceinline__ float rcpa(float x) {
    float y; asm("rcp.approx.ftz.f32 %0, %1;" : "=f"(y) : "f"(x)); return y;
}
__device__ __forceinline__ float ex2a(float x) {
    float y; asm("ex2.approx.ftz.f32 %0, %1;" : "=f"(y) : "f"(x)); return y;
}
// ---- packed f32x2 helpers (FFMA2 path: PTX-only on sm_103a) ----
__device__ __forceinline__ u64 pk(float lo, float hi) {
    u64 r; asm("mov.b64 %0, {%1, %2};" : "=l"(r) : "f"(lo), "f"(hi)); return r;
}
__device__ __forceinline__ void upk(float& lo, float& hi, u64 v) {
    asm("mov.b64 {%0, %1}, %2;" : "=f"(lo), "=f"(hi) : "l"(v));
}
__device__ __forceinline__ u64 fma2(u64 a, u64 b, u64 c) {
    u64 r; asm("fma.rn.f32x2 %0, %1, %2, %3;" : "=l"(r) : "l"(a), "l"(b), "l"(c));
    return r;
}
__device__ __forceinline__ u64 mul2(u64 a, u64 b) {
    u64 r; asm("mul.rn.f32x2 %0, %1, %2;" : "=l"(r) : "l"(a), "l"(b)); return r;
}

extern __shared__ float smem[];

__global__ void __launch_bounds__(64)
bm_kernel(const float* __restrict__ x0g,
          const float* __restrict__ ug,
          const float* __restrict__ lamg,
          float* __restrict__ outg)
{
    const int tid  = threadIdx.x;
    const int lane = tid & 31;
    const int wid  = tid >> 5;                 // 0 or 1 -> SMSP 0 / 1
    const int b0   = blockIdx.x * 64 + wid * 32;
    const int b    = b0 + lane;

    float* ub = smem + wid * WARP_WORDS;       // [3][32*ROWW] ring
    float* ob = ub + 3 * UBUF_WORDS;           // [2][32*OROWW]
    const uint32_t ubS = (uint32_t)__cvta_generic_to_shared(ub);

    const float e12 = expf(lamg[0]);
    const float e23 = expf(lamg[1]);
    const float ee0 = expf(lamg[2]),  ee1 = expf(lamg[3]),  ee2 = expf(lamg[4]);
    const float es0 = expf(lamg[5]),  es1 = expf(lamg[6]),  es2 = expf(lamg[7]);
    const float eh0 = expf(lamg[8]),  eh1 = expf(lamg[9]),  eh2 = expf(lamg[10]);
    const float ec0 = expf(lamg[11]), ec1 = expf(lamg[12]), ec2 = expf(lamg[13]);

    const float kl0 = (float)(60.0 / 10665991.0 * 1.4426950408889634);
    const float kl1 = (float)(60.0 / 27000000.0 * 1.4426950408889634);
    const float kl2 = (float)(60.0 /  7953253.0 * 1.4426950408889634);

    const float ng12_1 = -kl1 * e12;
    const float g23_1  =  kl1 * e23;
    const float eeK1 = kl1*ee1, neeK1 = -eeK1;
    const float esK1 = kl1*es1, ehK1 = kl1*eh1, ecK1 = kl1*ec1;

    // packed constants for states (0,2)
    const u64 G02    = pk( kl0 * e12, -kl2 * e23);
    const u64 eeK02  = pk( kl0*ee0,  kl2*ee2);
    const u64 neeK02 = pk(-kl0*ee0, -kl2*ee2);
    const u64 esK02  = pk( kl0*es0,  kl2*es2);
    const u64 ehK02  = pk( kl0*eh0,  kl2*eh2);
    const u64 ecK02  = pk( kl0*ec0,  kl2*ec2);
    const u64 P3P3   = pk(-0.05550410866f, -0.05550410866f);
    const u64 P2P2   = pk( 0.24022650696f,  0.24022650696f);
    const u64 P1P1   = pk(-0.69314718056f, -0.69314718056f);
    const u64 ONE2   = pk(1.0f, 1.0f);

    float x0 = x0g[b * 3 + 0];
    float x1 = x0g[b * 3 + 1];
    float x2 = x0g[b * 3 + 2];
    float i0 = rcpa(x0), i1 = rcpa(x1), i2 = rcpa(x2);
    i0 = i0 * (2.0f - x0 * i0);
    i1 = i1 * (2.0f - x1 * i1);
    i2 = i2 * (2.0f - x2 * i2);

    u64 X02 = pk(x0, x2);        // packed persistent state (0,2)
    u64 I02 = pk(i0, i2);

    const float* up0 = ug + (size_t)b0 * USTRIDE;   // warp's chain-0 u base

    // Serialized staging for priming only.
#define STAGE_FULL(C, SLOT) do {                                              \
    uint32_t s = ubS + (SLOT) * (UBUF_WORDS * 4) + lane * 16;                 \
    const float* g = up0 + (size_t)(C) * (CHUNK * 8) + lane * 4;              \
    _Pragma("unroll")                                                         \
    for (int i_ = 0; i_ < 32; i_++) {                                         \
        cpa16(s, g);                                                          \
        s += ROWW * 4;                                                        \
        g += USTRIDE;                                                         \
    }                                                                         \
    cpa_commit();                                                             \
} while (0)

    STAGE_FULL(0, 0);
    STAGE_FULL(1, 1);
    cpa_wait1();               // chunk 0 resident
    __syncwarp();

    int rd = 0;                // ring slot holding chunk c
    for (int c = 0; c < NCHUNK; c++) {
        const int bo  = c & 1;               // ob buffer for this chunk
        const int wrs = (rd + 2 >= 3) ? rd - 1 : rd + 2;  // slot for chunk c+2
        const bool stage_on = (c + 2 < NCHUNK);
        const bool drain_on = (c > 0);

        const float*  row   = &ub[rd * UBUF_WORDS + lane * ROWW];
        float*        orow  = &ob[bo * OBUF_WORDS + lane * OROWW];
        const float*  obpre = &ob[(bo ^ 1) * OBUF_WORDS];
        const uint32_t ubN  = ubS + wrs * (UBUF_WORDS * 4) + lane * 16;
        const float*  usN   = up0 + (size_t)(c + 2) * (CHUNK * 8) + lane * 4;
        float*        gpre  = outg + (size_t)(c - 1) * (CHUNK * 3);

        float sb[12];          // 4 steps x 3 comps, masked, reg-resident

        float4 ua = *(const float4*)(row);        // u0,u1,h0,h1
        float4 uc = *(const float4*)(row + 4);    // h2,c0,c1,c2

#pragma unroll
        for (int j = 0; j < CHUNK; j++) {
            // stage 2 chain-rows of chunk c+2 (engine-paced, off-chain)
            if (stage_on) {
                cpa16(ubN + (2*j)     * (ROWW * 4), usN + (size_t)(2*j)     * USTRIDE);
                cpa16(ubN + (2*j + 1) * (ROWW * 4), usN + (size_t)(2*j + 1) * USTRIDE);
            }
            // drain one coalesced 16B unit of chunk c-1 per step (12 of 16)
            if (drain_on && j < 12) {
                const int unit  = j * 32 + lane;
                const int chain = unit / 12;
                const int o     = unit - chain * 12;
                const float4 v = *(const float4*)(obpre + chain * OROWW + o * 4);
                *(float4*)(gpre + (size_t)(b0 + chain) * OSTRIDE + o * 4) = v;
            }

            float4 na, nc;
            if (j < CHUNK - 1) {
                na = *(const float4*)(row + (j + 1) * 8);
                nc = *(const float4*)(row + (j + 1) * 8 + 4);
            }

            // out row 16c+j <- current state, masked by u0 of this row
            {
                const bool nm = (c == 0) && (j == 0);
                const bool mv = !nm && (ua.x < 1e-6f);
                const int  s  = (j & 3) * 3;
                sb[s + 0] = mv ? -1.0f : x0;
                sb[s + 1] = mv ? -1.0f : x1;
                sb[s + 2] = mv ? -1.0f : x2;
            }

            // ---- scan step: states (0,2) packed f32x2, state 1 scalar ----
            const u64 H02 = pk(ua.z, uc.x);          // (h0, h2)
            const u64 C02 = pk(uc.y, uc.w);          // (c0, c2)
            const u64 U11 = pk(ua.y, ua.y);          // (u1, u1)
            const u64 U00 = pk(ua.x, ua.x);          // (u0, u0)

            u64 w02 = fma2(ecK02, C02, neeK02);
            w02 = fma2(ehK02, H02, w02);
            w02 = fma2(esK02, U11, w02);
            const u64 eu02 = mul2(eeK02, U00);
            const u64 q02  = fma2(eu02, I02, w02);

            const float d12 = i0 - i1;
            const float d23 = i1 - i2;
            const u64 D   = pk(d12, d23);
            const u64 X11 = pk(x1, x1);
            const u64 t02 = mul2(G02, D);
            const u64 m02 = fma2(t02, X11, q02);
            float m0, m2; upk(m0, m2, m02);

            // scalar state 1
            const float w1 = fmaf(esK1, ua.y, fmaf(ehK1, ua.w, fmaf(ecK1, uc.z, neeK1)));
            const float q1 = fmaf(eeK1 * ua.x, i1, w1);
            const float m1 = fmaf(g23_1 * d23, x2, fmaf(ng12_1 * d12, x0, q1));

            // 2^-m cubic
            u64 r02 = fma2(P3P3, m02, P2P2);
            r02 = fma2(r02, m02, P1P1);
            r02 = fma2(r02, m02, ONE2);
            const float r1 = fmaf(fmaf(fmaf(-0.05550410866f, m1, 0.24022650696f), m1, -0.69314718056f), m1, 1.0f);

            // state updates
            X02 = mul2(X02, pk(ex2a(m0), ex2a(m2)));
            x1 *= ex2a(m1);
            I02 = mul2(I02, r02);
            i1 *= r1;
            upk(x0, x2, X02);
            upk(i0, i2, I02);

            ua = na; uc = nc;

            // flush 4 buffered steps: 3x STS.128, conflict-free at stride 52
            if ((j & 3) == 3) {
                float* dst = orow + (j - 3) * 3;
                *(float4*)(dst + 0) = make_float4(sb[0], sb[1], sb[2],  sb[3]);
                *(float4*)(dst + 4) = make_float4(sb[4], sb[5], sb[6],  sb[7]);
                *(float4*)(dst + 8) = make_float4(sb[8], sb[9], sb[10], sb[11]);
            }
        }

        cpa_commit();          // close group for chunk c+2 (possibly empty)
        cpa_wait1();           // chunk c+1 resident (c+2 may still fly)
        __syncwarp();          // ob[bo] visible for next chunk's cross-lane drain

        rd = (rd + 1 >= 3) ? 0 : rd + 1;
    }

    // drain the final chunk (NCHUNK-1, ob buffer 1) synchronously
    {
        const float* obl = &ob[1 * OBUF_WORDS];
        float* gl = outg + (size_t)(NCHUNK - 1) * (CHUNK * 3);
#pragma unroll
        for (int it = 0; it < 12; it++) {
            const int unit  = it * 32 + lane;
            const int chain = unit / 12;
            const int o     = unit - chain * 12;
            const float4 v = *(const float4*)(obl + chain * OROWW + o * 4);
            *(float4*)(gl + (size_t)(b0 + chain) * OSTRIDE + o * 4) = v;
        }
    }
}

extern "C" void kernel_launch(void* const* d_in, const int* in_sizes, int n_in,
                              void* d_out, int out_size)
{
    const float* x0  = nullptr;
    const float* u   = nullptr;
    const float* lam = nullptr;
    for (int i = 0; i < n_in; i++) {
        if (in_sizes[i] == 14)               lam = (const float*)d_in[i];
        else if (in_sizes[i] == BATCH * 3)   x0  = (const float*)d_in[i];
        else                                 u   = (const float*)d_in[i];
    }
    cudaFuncSetAttribute(bm_kernel,
                         cudaFuncAttributeMaxDynamicSharedMemorySize,
                         SMEM_BYTES);
    bm_kernel<<<BATCH / 64, 64, SMEM_BYTES>>>(x0, u, lam, (float*)d_out);
}